// round 5
// baseline (speedup 1.0000x reference)
#include <cuda_runtime.h>
#include <cstdint>

// BinCat: idx = sum_j (1 - x[b,i,j]) * 2^(19-j), out[row,:] = cats[idx,:]
// x:    (4096, 16, 20) int32 (0/1)   -> 65536 rows of 80 B (16B-aligned)
// cats: (2^20, 64) float32           -> 256 B rows (256B-aligned)
// out:  (4096, 16, 64) float32
//
// R5: async bulk-copy gather (FlashMLA sparse-KV pattern).
//   Per CTA (64 rows, 64 threads):
//     1. thread t computes idx of row base+t (5 independent int4 loads).
//     2. thread t issues cp.async.bulk (256 B) cats[idx] -> smem slot t,
//        completing on a shared mbarrier (expect_tx = 16 KB).
//     3. mbarrier wait, then ONE 16 KB contiguous bulk store smem -> out.
//   The async engine holds the gather MLP (64 reqs/CTA, ~7 CTAs/SM resident)
//   instead of warp registers/scoreboards, which R4 showed was the limiter
//   (DRAM 31%, L1 23%, issue 19% -- nothing saturated => in-flight-bound).

static constexpr int LENGTH        = 20;
static constexpr int DIM           = 64;
static constexpr int ROW_BYTES     = DIM * 4;                 // 256
static constexpr int ROWS_PER_CTA  = 64;
static constexpr int THREADS       = 64;
static constexpr int TILE_BYTES    = ROWS_PER_CTA * ROW_BYTES; // 16384

__global__ void __launch_bounds__(THREADS)
bincat_bulk_kernel(const int* __restrict__ x,
                   const float* __restrict__ cats,
                   float* __restrict__ out,
                   int nrows)
{
    __shared__ alignas(256) unsigned char tile[TILE_BYTES];
    __shared__ alignas(8)  unsigned long long mbar;

    const int t    = threadIdx.x;
    const int row0 = blockIdx.x * ROWS_PER_CTA;
    if (row0 >= nrows) return;

    const int cnt = (nrows - row0 < ROWS_PER_CTA) ? (nrows - row0) : ROWS_PER_CTA;

    const uint32_t mbar_addr = (uint32_t)__cvta_generic_to_shared(&mbar);
    const uint32_t tile_addr = (uint32_t)__cvta_generic_to_shared(tile);

    // ---- init mbarrier (count = 1: the expect_tx arrival) ----
    if (t == 0) {
        asm volatile("mbarrier.init.shared.b64 [%0], %1;"
                     :: "r"(mbar_addr), "r"(1) : "memory");
    }
    __syncthreads();

    // ---- compute this thread's row index (rows are 80 B = 5 x int4) ----
    unsigned idx = 0u;
    const int row = row0 + t;
    if (t < cnt) {
        const int4* __restrict__ xr =
            reinterpret_cast<const int4*>(x + (size_t)row * LENGTH);
        const int4 a0 = __ldg(&xr[0]);
        const int4 a1 = __ldg(&xr[1]);
        const int4 a2 = __ldg(&xr[2]);
        const int4 a3 = __ldg(&xr[3]);
        const int4 a4 = __ldg(&xr[4]);
        const int v[LENGTH] = { a0.x, a0.y, a0.z, a0.w,
                                a1.x, a1.y, a1.z, a1.w,
                                a2.x, a2.y, a2.z, a2.w,
                                a3.x, a3.y, a3.z, a3.w,
                                a4.x, a4.y, a4.z, a4.w };
        #pragma unroll
        for (int j = 0; j < LENGTH; ++j)
            idx |= (unsigned)(1 - v[j]) << (LENGTH - 1 - j);
    }

    // ---- post expected tx bytes, then everyone issues their 256B gather ----
    if (t == 0) {
        asm volatile("mbarrier.arrive.expect_tx.shared.b64 _, [%0], %1;"
                     :: "r"(mbar_addr), "r"((unsigned)(cnt * ROW_BYTES))
                     : "memory");
    }
    __syncthreads();   // expect_tx visible before any complete_tx can race it

    if (t < cnt) {
        const uint32_t dst = tile_addr + (uint32_t)t * ROW_BYTES;
        const void* src = (const void*)(cats + (size_t)idx * DIM);
        asm volatile(
            "cp.async.bulk.shared::cluster.global.mbarrier::complete_tx::bytes "
            "[%0], [%1], %2, [%3];"
            :: "r"(dst), "l"(src), "r"((unsigned)ROW_BYTES), "r"(mbar_addr)
            : "memory");
    }

    // ---- wait for all 64 rows (parity 0, single-phase use) ----
    {
        asm volatile(
            "{\n\t"
            ".reg .pred P1;\n\t"
            "WAIT_LOOP_%=:\n\t"
            "mbarrier.try_wait.parity.shared.b64 P1, [%0], %1, 0x989680;\n\t"
            "@P1 bra.uni WAIT_DONE_%=;\n\t"
            "bra.uni WAIT_LOOP_%=;\n\t"
            "WAIT_DONE_%=:\n\t"
            "}"
            :: "r"(mbar_addr), "r"(0u) : "memory");
    }

    // ---- single contiguous bulk store: smem tile -> out[row0*DIM ...] ----
    if (t == 0) {
        float* dstg = out + (size_t)row0 * DIM;
        asm volatile(
            "cp.async.bulk.global.shared::cta.bulk_group [%0], [%1], %2;"
            :: "l"(dstg), "r"(tile_addr), "r"((unsigned)(cnt * ROW_BYTES))
            : "memory");
        asm volatile("cp.async.bulk.commit_group;" ::: "memory");
        asm volatile("cp.async.bulk.wait_group.read 0;" ::: "memory");
    }
}

extern "C" void kernel_launch(void* const* d_in, const int* in_sizes, int n_in,
                              void* d_out, int out_size)
{
    const int*   x    = (const int*)d_in[0];    // (B, I, 20) int32
    const float* cats = (const float*)d_in[1];  // (2^20, 64) float32
    float*       out  = (float*)d_out;          // (B, I, 64) float32

    const int nrows  = in_sizes[0] / LENGTH;    // 65536
    const int blocks = (nrows + ROWS_PER_CTA - 1) / ROWS_PER_CTA;  // 1024

    bincat_bulk_kernel<<<blocks, THREADS>>>(x, cats, out, nrows);
}